// round 5
// baseline (speedup 1.0000x reference)
#include <cuda_runtime.h>

#define GEMM_M 2400
#define GEMM_N 16384
#define GEMM_K 256
#define BM 128
#define BN 128
#define BK 16

// 2400 * 16384 floats = 157 MB scratch for the dynamic weights w
__device__ float g_wbuf[(size_t)GEMM_M * GEMM_N];

// ---------------- f32x2 packed helpers (Blackwell packed fp32 pipe) ----------------
__device__ __forceinline__ unsigned long long f2pack(float lo, float hi) {
    unsigned long long r;
    asm("mov.b64 %0, {%1, %2};" : "=l"(r) : "f"(lo), "f"(hi));
    return r;
}
__device__ __forceinline__ void f2unpack(unsigned long long v, float& lo, float& hi) {
    asm("mov.b64 {%0, %1}, %2;" : "=f"(lo), "=f"(hi) : "l"(v));
}
__device__ __forceinline__ unsigned long long ffma2(unsigned long long a,
                                                    unsigned long long b,
                                                    unsigned long long c) {
    unsigned long long d;
    asm("fma.rn.f32x2 %0, %1, %2, %3;" : "=l"(d) : "l"(a), "l"(b), "l"(c));
    return d;
}

// ======================= Kernel A: w = qc @ W_gen + bias =======================
__global__ __launch_bounds__(256, 2)
void gen_w_kernel(const float* __restrict__ Q,     // [2400, 256]
                  const float* __restrict__ W,     // [256, 16384]
                  const float* __restrict__ bias,  // [16384]
                  float* __restrict__ out)         // [2400, 16384]
{
    __shared__ float As[2][BK][BM];   // A stored transposed: As[k][m]
    __shared__ float Bs[2][BK][BN];

    const int tid  = threadIdx.x;
    const int tx   = tid & 15;
    const int ty   = tid >> 4;
    const int row0 = blockIdx.y * BM;
    const int col0 = blockIdx.x * BN;

    // ---- global-load mappings (each thread: 2 consecutive float4) ----
    const int aRow = tid >> 1;          // 0..127
    const int aQ   = (tid & 1) * 2;     // k-quad base: 0 or 2
    const int bRow = tid >> 4;          // 0..15
    const int bQ   = (tid & 15) * 2;    // n-quad base: 0..30

    float4 aR[2], bR[2];

    const bool aValid = (row0 + aRow) < GEMM_M;
    const float* aPtr = Q + (size_t)(row0 + aRow) * GEMM_K + aQ * 4;
    const float* bPtr = W + (size_t)bRow * GEMM_N + col0 + bQ * 4;

    unsigned long long acc[8][4];
#pragma unroll
    for (int i = 0; i < 8; ++i)
#pragma unroll
        for (int j = 0; j < 4; ++j) acc[i][j] = 0ull;

    // prologue: load tile 0
    if (aValid) {
        aR[0] = *(const float4*)(aPtr + 0);
        aR[1] = *(const float4*)(aPtr + 4);
    } else {
        aR[0] = make_float4(0.f, 0.f, 0.f, 0.f);
        aR[1] = aR[0];
    }
    bR[0] = *(const float4*)(bPtr + 0);
    bR[1] = *(const float4*)(bPtr + 4);

#pragma unroll
    for (int s = 0; s < 2; ++s) {
        As[0][aQ * 4 + s * 4 + 0][aRow] = (s == 0) ? aR[0].x : aR[1].x;
        As[0][aQ * 4 + s * 4 + 1][aRow] = (s == 0) ? aR[0].y : aR[1].y;
        As[0][aQ * 4 + s * 4 + 2][aRow] = (s == 0) ? aR[0].z : aR[1].z;
        As[0][aQ * 4 + s * 4 + 3][aRow] = (s == 0) ? aR[0].w : aR[1].w;
    }
    *(float4*)&Bs[0][bRow][(bQ + 0) * 4] = bR[0];
    *(float4*)&Bs[0][bRow][(bQ + 1) * 4] = bR[1];
    __syncthreads();

    const int nTiles = GEMM_K / BK;  // 16
#pragma unroll 1
    for (int t = 0; t < nTiles; ++t) {
        const int buf = t & 1;
        if (t + 1 < nTiles) {
            const int kk = (t + 1) * BK;
            if (aValid) {
                aR[0] = *(const float4*)(aPtr + kk + 0);
                aR[1] = *(const float4*)(aPtr + kk + 4);
            }
            bR[0] = *(const float4*)(bPtr + (size_t)kk * GEMM_N + 0);
            bR[1] = *(const float4*)(bPtr + (size_t)kk * GEMM_N + 4);
        }

#pragma unroll
        for (int k = 0; k < BK; ++k) {
            float4 a0 = *(const float4*)&As[buf][k][ty * 8];
            float4 a1 = *(const float4*)&As[buf][k][ty * 8 + 4];
            float4 b0 = *(const float4*)&Bs[buf][k][tx * 4];
            float4 b1 = *(const float4*)&Bs[buf][k][64 + tx * 4];
            unsigned long long bp0 = f2pack(b0.x, b0.y);
            unsigned long long bp1 = f2pack(b0.z, b0.w);
            unsigned long long bp2 = f2pack(b1.x, b1.y);
            unsigned long long bp3 = f2pack(b1.z, b1.w);
            float av[8] = {a0.x, a0.y, a0.z, a0.w, a1.x, a1.y, a1.z, a1.w};
#pragma unroll
            for (int i = 0; i < 8; ++i) {
                unsigned long long ad = f2pack(av[i], av[i]);
                acc[i][0] = ffma2(ad, bp0, acc[i][0]);
                acc[i][1] = ffma2(ad, bp1, acc[i][1]);
                acc[i][2] = ffma2(ad, bp2, acc[i][2]);
                acc[i][3] = ffma2(ad, bp3, acc[i][3]);
            }
        }

        if (t + 1 < nTiles) {
            const int nbuf = buf ^ 1;
#pragma unroll
            for (int s = 0; s < 2; ++s) {
                As[nbuf][aQ * 4 + s * 4 + 0][aRow] = (s == 0) ? aR[0].x : aR[1].x;
                As[nbuf][aQ * 4 + s * 4 + 1][aRow] = (s == 0) ? aR[0].y : aR[1].y;
                As[nbuf][aQ * 4 + s * 4 + 2][aRow] = (s == 0) ? aR[0].z : aR[1].z;
                As[nbuf][aQ * 4 + s * 4 + 3][aRow] = (s == 0) ? aR[0].w : aR[1].w;
            }
            *(float4*)&Bs[nbuf][bRow][(bQ + 0) * 4] = bR[0];
            *(float4*)&Bs[nbuf][bRow][(bQ + 1) * 4] = bR[1];
            __syncthreads();
        }
    }

    // epilogue: unpack, add bias, store
#pragma unroll
    for (int i = 0; i < 8; ++i) {
        const int r = row0 + ty * 8 + i;
        if (r >= GEMM_M) continue;
        const size_t rb = (size_t)r * GEMM_N;
        const int c0 = col0 + tx * 4;
        const int c1 = col0 + 64 + tx * 4;
        float4 v;
        f2unpack(acc[i][0], v.x, v.y);
        f2unpack(acc[i][1], v.z, v.w);
        v.x += __ldg(&bias[c0 + 0]);
        v.y += __ldg(&bias[c0 + 1]);
        v.z += __ldg(&bias[c0 + 2]);
        v.w += __ldg(&bias[c0 + 3]);
        *(float4*)(out + rb + c0) = v;
        f2unpack(acc[i][2], v.x, v.y);
        f2unpack(acc[i][3], v.z, v.w);
        v.x += __ldg(&bias[c1 + 0]);
        v.y += __ldg(&bias[c1 + 1]);
        v.z += __ldg(&bias[c1 + 2]);
        v.w += __ldg(&bias[c1 + 3]);
        *(float4*)(out + rb + c1) = v;
    }
}

// ================= Kernel B: mixing + LayerNorm + ReLU (one CTA per query) =================
// smem: ws[256][68] (pitch-padded, conflict-free float4 row reads) + xs[32][256]
#define WS_PITCH 68
#define SMEM_B_BYTES (256 * WS_PITCH * 4 + 32 * 256 * 4)

__global__ __launch_bounds__(256)
void mix_ln_kernel(const float* __restrict__ x,      // [2400, 32, 256]
                   const float* __restrict__ wbuf,   // [2400, 16384]
                   const float* __restrict__ gamma,  // [256]
                   const float* __restrict__ beta,   // [256]
                   float* __restrict__ out)          // [2400, 32, 256]
{
    extern __shared__ float sm[];
    float* ws = sm;                      // 256 * 68
    float* xs = sm + 256 * WS_PITCH;     // 32 * 256

    const int tid  = threadIdx.x;
    const int bid  = blockIdx.x;
    const int lane = tid & 31;
    const int warp = tid >> 5;
    const size_t wbase = (size_t)bid * 16384;
    const size_t xbase = (size_t)bid * 8192;

    // stage w: 16384 floats -> ws[c][d], pitch 68
#pragma unroll
    for (int ch = 0; ch < 16; ++ch) {
        const int idx = ch * 1024 + tid * 4;
        float4 v = *(const float4*)(wbuf + wbase + idx);
        *(float4*)&ws[(idx >> 6) * WS_PITCH + (idx & 63)] = v;
    }
    // stage x: 8192 floats
#pragma unroll
    for (int ch = 0; ch < 8; ++ch) {
        const int idx = ch * 1024 + tid * 4;
        *(float4*)&xs[idx] = *(const float4*)(x + xbase + idx);
    }
    __syncthreads();

    // warp handles p in [warp*4, warp*4+4); lane handles channels c = lane + 32*j
    const int p0 = warp * 4;
    float acc[4][8];
#pragma unroll
    for (int pp = 0; pp < 4; ++pp)
#pragma unroll
        for (int j = 0; j < 8; ++j) acc[pp][j] = 0.f;

    const int wrow0 = lane * WS_PITCH;

#pragma unroll 4
    for (int dq = 0; dq < 16; ++dq) {
        float4 wv[8];
#pragma unroll
        for (int j = 0; j < 8; ++j)
            wv[j] = *(const float4*)&ws[wrow0 + j * (32 * WS_PITCH) + dq * 4];
#pragma unroll
        for (int pp = 0; pp < 4; ++pp) {
            const float* xr = xs + (p0 + pp) * 256 + dq * 4;
#pragma unroll
            for (int g = 0; g < 4; ++g) {
                float4 xv = *(const float4*)&xr[g * 64];
                const int j0 = 2 * g;
                acc[pp][j0]     = fmaf(wv[j0].x, xv.x, acc[pp][j0]);
                acc[pp][j0]     = fmaf(wv[j0].y, xv.y, acc[pp][j0]);
                acc[pp][j0]     = fmaf(wv[j0].z, xv.z, acc[pp][j0]);
                acc[pp][j0]     = fmaf(wv[j0].w, xv.w, acc[pp][j0]);
                acc[pp][j0 + 1] = fmaf(wv[j0 + 1].x, xv.x, acc[pp][j0 + 1]);
                acc[pp][j0 + 1] = fmaf(wv[j0 + 1].y, xv.y, acc[pp][j0 + 1]);
                acc[pp][j0 + 1] = fmaf(wv[j0 + 1].z, xv.z, acc[pp][j0 + 1]);
                acc[pp][j0 + 1] = fmaf(wv[j0 + 1].w, xv.w, acc[pp][j0 + 1]);
            }
        }
    }

    // gamma/beta for this lane's 8 channels
    float gch[8], bch[8];
#pragma unroll
    for (int j = 0; j < 8; ++j) {
        const int c = lane + 32 * j;
        gch[j] = __ldg(&gamma[c]);
        bch[j] = __ldg(&beta[c]);
    }

    // LayerNorm over C=256 per p (distributed across the warp) + ReLU
#pragma unroll
    for (int pp = 0; pp < 4; ++pp) {
        float s1 = 0.f, s2 = 0.f;
#pragma unroll
        for (int j = 0; j < 8; ++j) {
            s1 += acc[pp][j];
            s2 += acc[pp][j] * acc[pp][j];
        }
#pragma unroll
        for (int off = 16; off > 0; off >>= 1) {
            s1 += __shfl_xor_sync(0xFFFFFFFFu, s1, off);
            s2 += __shfl_xor_sync(0xFFFFFFFFu, s2, off);
        }
        const float mu  = s1 * (1.f / 256.f);
        const float var = s2 * (1.f / 256.f) - mu * mu;
        const float rs  = rsqrtf(var + 1e-5f);
        const size_t ob = xbase + (size_t)(p0 + pp) * 256;
#pragma unroll
        for (int j = 0; j < 8; ++j) {
            const int c = lane + 32 * j;
            float v = (acc[pp][j] - mu) * rs * gch[j] + bch[j];
            out[ob + c] = fmaxf(v, 0.f);
        }
    }
}

// ============================== launch ==============================
extern "C" void kernel_launch(void* const* d_in, const int* in_sizes, int n_in,
                              void* d_out, int out_size) {
    const float* x     = (const float*)d_in[0];  // [8,300,32,256]
    const float* qc    = (const float*)d_in[1];  // [8,300,256]
    const float* Wg    = (const float*)d_in[2];  // [256,16384]
    const float* bg    = (const float*)d_in[3];  // [16384]
    const float* gamma = (const float*)d_in[4];  // [256]
    const float* beta  = (const float*)d_in[5];  // [256]
    float* out = (float*)d_out;

    float* wbuf = nullptr;
    cudaGetSymbolAddress((void**)&wbuf, g_wbuf);

    // Kernel A: dynamic weights
    dim3 gridA(GEMM_N / BN, (GEMM_M + BM - 1) / BM);  // (128, 19)
    gen_w_kernel<<<gridA, 256>>>(qc, Wg, bg, wbuf);

    // Kernel B: mixing + LN + ReLU
    cudaFuncSetAttribute(mix_ln_kernel, cudaFuncAttributeMaxDynamicSharedMemorySize,
                         SMEM_B_BYTES);
    mix_ln_kernel<<<GEMM_M, 256, SMEM_B_BYTES>>>(x, wbuf, gamma, beta, out);
}

// round 7
// speedup vs baseline: 1.7333x; 1.7333x over previous
#include <cuda_runtime.h>
#include <cuda_fp16.h>
#include <cstdint>

#define GEMM_M 2400
#define PAD_M  2432
#define GEMM_N 16384
#define GEMM_K 256

// ---------------- device scratch (no allocation allowed) ----------------
__device__ float  g_wbuf[(size_t)GEMM_M * GEMM_N];   // 157 MB dynamic weights
__device__ __half g_Ah[(size_t)PAD_M  * GEMM_K];     // qc hi   [2432,256]
__device__ __half g_Al[(size_t)PAD_M  * GEMM_K];     // qc lo
__device__ __half g_Bh[(size_t)GEMM_N * GEMM_K];     // W^T hi  [16384,256] K-major
__device__ __half g_Bl[(size_t)GEMM_N * GEMM_K];     // W^T lo

// ---------------- PTX helpers (baseline PTX only: sm_80-era ops) ----------------
__device__ __forceinline__ uint32_t smem_u32(const void* p) {
    uint32_t a;
    asm("{ .reg .u64 t; cvta.to.shared.u64 t, %1; cvt.u32.u64 %0, t; }" : "=r"(a) : "l"(p));
    return a;
}
__device__ __forceinline__ void cp16(uint32_t dst, const void* src) {
    asm volatile("cp.async.cg.shared.global [%0], [%1], 16;" :: "r"(dst), "l"(src) : "memory");
}
__device__ __forceinline__ void cp_commit() {
    asm volatile("cp.async.commit_group;" ::: "memory");
}
template <int N>
__device__ __forceinline__ void cp_wait() {
    asm volatile("cp.async.wait_group %0;" :: "n"(N) : "memory");
}
__device__ __forceinline__ void ldmatrix_x4(uint32_t& r0, uint32_t& r1, uint32_t& r2,
                                            uint32_t& r3, uint32_t addr) {
    asm volatile("ldmatrix.sync.aligned.m8n8.x4.shared.b16 {%0,%1,%2,%3}, [%4];"
                 : "=r"(r0), "=r"(r1), "=r"(r2), "=r"(r3) : "r"(addr));
}
__device__ __forceinline__ void mma16816(float* c, const uint32_t* a, const uint32_t* b) {
    asm volatile("mma.sync.aligned.m16n8k16.row.col.f32.f16.f16.f32 "
                 "{%0,%1,%2,%3}, {%4,%5,%6,%7}, {%8,%9}, {%0,%1,%2,%3};"
                 : "+f"(c[0]), "+f"(c[1]), "+f"(c[2]), "+f"(c[3])
                 : "r"(a[0]), "r"(a[1]), "r"(a[2]), "r"(a[3]), "r"(b[0]), "r"(b[1]));
}

// crosswise swizzle for a 128-row x 32-col fp16 tile (rows = 64B = 4 x 16B chunks).
// Packs 2 rows per 128B phase; XOR by (r>>1)&3 makes every ldmatrix 8-row
// wavefront hit 8 distinct 16B bank-groups (verified conflict-free).
__device__ __forceinline__ uint32_t swz(int r, int c) {
    return (uint32_t)(((r >> 1) << 7) + ((r & 1) << 6) + ((c ^ ((r >> 1) & 3)) << 4));
}

// ======================= split/prep kernels =======================
__global__ void split_qc_kernel(const float* __restrict__ qc,
                                __half* __restrict__ Ah, __half* __restrict__ Al) {
    int idx = blockIdx.x * blockDim.x + threadIdx.x;
    if (idx >= PAD_M * GEMM_K) return;
    float v = (idx < GEMM_M * GEMM_K) ? qc[idx] : 0.f;
    __half h = __float2half_rn(v);
    float lo = v - __half2float(h);
    Ah[idx] = h;
    Al[idx] = __float2half_rn(lo);
}

__global__ void split_w_kernel(const float* __restrict__ W,
                               __half* __restrict__ Bh, __half* __restrict__ Bl) {
    __shared__ float sm[32][33];
    const int n0 = blockIdx.x * 32;
    const int k0 = blockIdx.y * 32;
    const int tx = threadIdx.x, ty = threadIdx.y;
    sm[ty][tx] = W[(size_t)(k0 + ty) * GEMM_N + n0 + tx];
    __syncthreads();
    float v = sm[tx][ty];  // = W[k0+tx][n0+ty]
    __half h = __float2half_rn(v);
    float lo = v - __half2float(h);
    const size_t o = (size_t)(n0 + ty) * GEMM_K + k0 + tx;
    Bh[o] = h;
    Bl[o] = __float2half_rn(lo);
}

// ======================= split-fp16 HMMA GEMM =======================
// D = Ah*Bh + Ah*Bl + Al*Bh (fp32 accum); dropped Al*Bl ~ 2^-22 relative.
#define TILE_BYTES  8192                 // 128 x 32 fp16
#define STAGE_BYTES (4 * TILE_BYTES)     // Ah | Al | Bh | Bl
#define SMEM_GEMM   (2 * STAGE_BYTES)    // 64 KB, 2 stages
#define NTILES      (GEMM_K / 32)        // 8

__device__ __forceinline__ void stage_load(uint32_t sbuf,
                                           const __half* __restrict__ gAh,
                                           const __half* __restrict__ gAl,
                                           const __half* __restrict__ gBh,
                                           const __half* __restrict__ gBl,
                                           int kc, int tid) {
#pragma unroll
    for (int t = 0; t < 2; ++t) {
        const int q = t * 256 + tid;      // chunk id 0..511
        const int r = q >> 2;
        const int c = q & 3;
        const uint32_t dst = swz(r, c);
        const size_t goff = (size_t)r * GEMM_K + kc + c * 8;
        cp16(sbuf + 0 * TILE_BYTES + dst, gAh + goff);
        cp16(sbuf + 1 * TILE_BYTES + dst, gAl + goff);
        cp16(sbuf + 2 * TILE_BYTES + dst, gBh + goff);
        cp16(sbuf + 3 * TILE_BYTES + dst, gBl + goff);
    }
}

__global__ __launch_bounds__(256)
void gen_w_mma_kernel(const __half* __restrict__ Ah, const __half* __restrict__ Al,
                      const __half* __restrict__ Bh, const __half* __restrict__ Bl,
                      const float* __restrict__ bias, float* __restrict__ out) {
    extern __shared__ char smem[];
    const uint32_t sbase = smem_u32(smem);
    const int tid  = threadIdx.x;
    const int wid  = tid >> 5;
    const int lane = tid & 31;
    const int n0 = blockIdx.x * 128;
    const int m0 = blockIdx.y * 128;
    const int warp_m = wid & 1;   // 2 warps along M (64 each)
    const int warp_n = wid >> 1;  // 4 warps along N (32 each)

    const __half* gAh = Ah + (size_t)m0 * GEMM_K;
    const __half* gAl = Al + (size_t)m0 * GEMM_K;
    const __half* gBh = Bh + (size_t)n0 * GEMM_K;
    const __half* gBl = Bl + (size_t)n0 * GEMM_K;

    float acc[4][4][4];
#pragma unroll
    for (int i = 0; i < 4; ++i)
#pragma unroll
        for (int j = 0; j < 4; ++j)
#pragma unroll
            for (int k = 0; k < 4; ++k) acc[i][j][k] = 0.f;

    // prologue: fill both stages
    stage_load(sbase, gAh, gAl, gBh, gBl, 0, tid);
    cp_commit();
    stage_load(sbase + STAGE_BYTES, gAh, gAl, gBh, gBl, 32, tid);
    cp_commit();
    cp_wait<1>();
    __syncthreads();

    // per-lane ldmatrix address components (row/chunk within tile)
    const int aRow = warp_m * 64 + (lane & 15);   // + mi*16
    const int aSel = lane >> 4;                   // 0: k0-7, 1: k8-15
    const int bG   = lane >> 3;
    const int bRow = warp_n * 32 + ((bG >> 1) << 3) + (lane & 7);  // + ng*16
    const int bSel = bG & 1;

#pragma unroll 1
    for (int t = 0; t < NTILES; ++t) {
        const uint32_t buf = sbase + (uint32_t)(t & 1) * STAGE_BYTES;
        const uint32_t sAh = buf;
        const uint32_t sAl = buf + TILE_BYTES;
        const uint32_t sBh = buf + 2 * TILE_BYTES;
        const uint32_t sBl = buf + 3 * TILE_BYTES;

#pragma unroll
        for (int k16 = 0; k16 < 2; ++k16) {
            const int cA = k16 * 2 + aSel;
            const int cB = k16 * 2 + bSel;

            // B fragments: 2 ldmatrix.x4 per operand cover n=32
            uint32_t bH[4][2], bL[4][2];
#pragma unroll
            for (int ng = 0; ng < 2; ++ng) {
                const uint32_t off = swz(bRow + ng * 16, cB);
                uint32_t r0, r1, r2, r3;
                ldmatrix_x4(r0, r1, r2, r3, sBh + off);
                bH[2 * ng][0] = r0; bH[2 * ng][1] = r1;
                bH[2 * ng + 1][0] = r2; bH[2 * ng + 1][1] = r3;
                ldmatrix_x4(r0, r1, r2, r3, sBl + off);
                bL[2 * ng][0] = r0; bL[2 * ng][1] = r1;
                bL[2 * ng + 1][0] = r2; bL[2 * ng + 1][1] = r3;
            }

#pragma unroll
            for (int mi = 0; mi < 4; ++mi) {
                const uint32_t off = swz(aRow + mi * 16, cA);
                uint32_t aH[4], aL[4];
                ldmatrix_x4(aH[0], aH[1], aH[2], aH[3], sAh + off);
                ldmatrix_x4(aL[0], aL[1], aL[2], aL[3], sAl + off);
#pragma unroll
                for (int ni = 0; ni < 4; ++ni) {
                    mma16816(acc[mi][ni], aH, bH[ni]);
                    mma16816(acc[mi][ni], aH, bL[ni]);
                    mma16816(acc[mi][ni], aL, bH[ni]);
                }
            }
        }

        __syncthreads();  // all warps done reading this buffer
        if (t + 2 < NTILES) {
            stage_load(buf, gAh, gAl, gBh, gBl, (t + 2) * 32, tid);
            cp_commit();
            cp_wait<1>();   // stage t+1 copies (this thread's) complete
        } else if (t + 1 < NTILES) {
            cp_wait<0>();
        }
        __syncthreads();
    }

    // epilogue: bias + store (fp32)
#pragma unroll
    for (int mi = 0; mi < 4; ++mi) {
        const int m_lo = m0 + warp_m * 64 + mi * 16 + (lane >> 2);
        const int m_hi = m_lo + 8;
#pragma unroll
        for (int ni = 0; ni < 4; ++ni) {
            const int n = n0 + warp_n * 32 + ni * 8 + (lane & 3) * 2;
            const float2 bv = *(const float2*)(bias + n);
            if (m_lo < GEMM_M) {
                float2 v;
                v.x = acc[mi][ni][0] + bv.x;
                v.y = acc[mi][ni][1] + bv.y;
                *(float2*)(out + (size_t)m_lo * GEMM_N + n) = v;
            }
            if (m_hi < GEMM_M) {
                float2 v;
                v.x = acc[mi][ni][2] + bv.x;
                v.y = acc[mi][ni][3] + bv.y;
                *(float2*)(out + (size_t)m_hi * GEMM_N + n) = v;
            }
        }
    }
}

// ================= Kernel B: mixing + LayerNorm + ReLU (one CTA per query) =================
#define WS_PITCH 68
#define SMEM_B_BYTES (256 * WS_PITCH * 4 + 32 * 256 * 4)

__global__ __launch_bounds__(256)
void mix_ln_kernel(const float* __restrict__ x,      // [2400, 32, 256]
                   const float* __restrict__ wbuf,   // [2400, 16384]
                   const float* __restrict__ gamma,  // [256]
                   const float* __restrict__ beta,   // [256]
                   float* __restrict__ out)          // [2400, 32, 256]
{
    extern __shared__ float sm[];
    float* ws = sm;                      // 256 * 68
    float* xs = sm + 256 * WS_PITCH;     // 32 * 256

    const int tid  = threadIdx.x;
    const int bid  = blockIdx.x;
    const int lane = tid & 31;
    const int warp = tid >> 5;
    const size_t wbase = (size_t)bid * 16384;
    const size_t xbase = (size_t)bid * 8192;

#pragma unroll
    for (int ch = 0; ch < 16; ++ch) {
        const int idx = ch * 1024 + tid * 4;
        float4 v = *(const float4*)(wbuf + wbase + idx);
        *(float4*)&ws[(idx >> 6) * WS_PITCH + (idx & 63)] = v;
    }
#pragma unroll
    for (int ch = 0; ch < 8; ++ch) {
        const int idx = ch * 1024 + tid * 4;
        *(float4*)&xs[idx] = *(const float4*)(x + xbase + idx);
    }
    __syncthreads();

    const int p0 = warp * 4;
    float acc[4][8];
#pragma unroll
    for (int pp = 0; pp < 4; ++pp)
#pragma unroll
        for (int j = 0; j < 8; ++j) acc[pp][j] = 0.f;

    const int wrow0 = lane * WS_PITCH;

#pragma unroll 4
    for (int dq = 0; dq < 16; ++dq) {
        float4 wv[8];
#pragma unroll
        for (int j = 0; j < 8; ++j)
            wv[j] = *(const float4*)&ws[wrow0 + j * (32 * WS_PITCH) + dq * 4];
#pragma unroll
        for (int pp = 0; pp < 4; ++pp) {
            const float* xr = xs + (p0 + pp) * 256 + dq * 4;
#pragma unroll
            for (int g = 0; g < 4; ++g) {
                float4 xv = *(const float4*)&xr[g * 64];
                const int j0 = 2 * g;
                acc[pp][j0]     = fmaf(wv[j0].x, xv.x, acc[pp][j0]);
                acc[pp][j0]     = fmaf(wv[j0].y, xv.y, acc[pp][j0]);
                acc[pp][j0]     = fmaf(wv[j0].z, xv.z, acc[pp][j0]);
                acc[pp][j0]     = fmaf(wv[j0].w, xv.w, acc[pp][j0]);
                acc[pp][j0 + 1] = fmaf(wv[j0 + 1].x, xv.x, acc[pp][j0 + 1]);
                acc[pp][j0 + 1] = fmaf(wv[j0 + 1].y, xv.y, acc[pp][j0 + 1]);
                acc[pp][j0 + 1] = fmaf(wv[j0 + 1].z, xv.z, acc[pp][j0 + 1]);
                acc[pp][j0 + 1] = fmaf(wv[j0 + 1].w, xv.w, acc[pp][j0 + 1]);
            }
        }
    }

    float gch[8], bch[8];
#pragma unroll
    for (int j = 0; j < 8; ++j) {
        const int c = lane + 32 * j;
        gch[j] = __ldg(&gamma[c]);
        bch[j] = __ldg(&beta[c]);
    }

#pragma unroll
    for (int pp = 0; pp < 4; ++pp) {
        float s1 = 0.f, s2 = 0.f;
#pragma unroll
        for (int j = 0; j < 8; ++j) {
            s1 += acc[pp][j];
            s2 += acc[pp][j] * acc[pp][j];
        }
#pragma unroll
        for (int off = 16; off > 0; off >>= 1) {
            s1 += __shfl_xor_sync(0xFFFFFFFFu, s1, off);
            s2 += __shfl_xor_sync(0xFFFFFFFFu, s2, off);
        }
        const float mu  = s1 * (1.f / 256.f);
        const float var = s2 * (1.f / 256.f) - mu * mu;
        const float rs  = rsqrtf(var + 1e-5f);
        const size_t ob = xbase + (size_t)(p0 + pp) * 256;
#pragma unroll
        for (int j = 0; j < 8; ++j) {
            const int c = lane + 32 * j;
            float v = (acc[pp][j] - mu) * rs * gch[j] + bch[j];
            out[ob + c] = fmaxf(v, 0.f);
        }
    }
}

// ============================== launch ==============================
extern "C" void kernel_launch(void* const* d_in, const int* in_sizes, int n_in,
                              void* d_out, int out_size) {
    const float* x     = (const float*)d_in[0];  // [8,300,32,256]
    const float* qc    = (const float*)d_in[1];  // [8,300,256]
    const float* Wg    = (const float*)d_in[2];  // [256,16384]
    const float* bg    = (const float*)d_in[3];  // [16384]
    const float* gamma = (const float*)d_in[4];  // [256]
    const float* beta  = (const float*)d_in[5];  // [256]
    float* out = (float*)d_out;

    float* wbuf = nullptr;
    cudaGetSymbolAddress((void**)&wbuf, g_wbuf);
    __half *ah, *al, *bh, *bl;
    cudaGetSymbolAddress((void**)&ah, g_Ah);
    cudaGetSymbolAddress((void**)&al, g_Al);
    cudaGetSymbolAddress((void**)&bh, g_Bh);
    cudaGetSymbolAddress((void**)&bl, g_Bl);

    // 1) fp16 hi/lo splits (+ transpose of W into [N,K] K-major)
    split_qc_kernel<<<(PAD_M * GEMM_K + 255) / 256, 256>>>(qc, ah, al);
    split_w_kernel<<<dim3(GEMM_N / 32, GEMM_K / 32), dim3(32, 32)>>>(Wg, bh, bl);

    // 2) split-fp16 HMMA GEMM: w = qc @ W_gen + bias
    cudaFuncSetAttribute(gen_w_mma_kernel, cudaFuncAttributeMaxDynamicSharedMemorySize,
                         SMEM_GEMM);
    dim3 gridG(GEMM_N / 128, (PAD_M) / 128);  // (128, 19)
    gen_w_mma_kernel<<<gridG, 256, SMEM_GEMM>>>(ah, al, bh, bl, bg, wbuf);

    // 3) mixing + LN + ReLU
    cudaFuncSetAttribute(mix_ln_kernel, cudaFuncAttributeMaxDynamicSharedMemorySize,
                         SMEM_B_BYTES);
    mix_ln_kernel<<<GEMM_M, 256, SMEM_B_BYTES>>>(x, wbuf, gamma, beta, out);
}

// round 11
// speedup vs baseline: 2.0201x; 1.1655x over previous
#include <cuda_runtime.h>
#include <cuda_fp16.h>
#include <cstdint>

#define GEMM_M 2400
#define PAD_M  2432
#define GEMM_N 16384
#define GEMM_K 256

// ---------------- device scratch (no allocation allowed) ----------------
__device__ __half g_Ah[(size_t)PAD_M  * GEMM_K];     // qc hi   [2432,256]
__device__ __half g_Al[(size_t)PAD_M  * GEMM_K];     // qc lo
__device__ __half g_Bh[(size_t)GEMM_N * GEMM_K];     // W^T hi  [16384,256] K-major
__device__ __half g_Bl[(size_t)GEMM_N * GEMM_K];     // W^T lo
__device__ __half g_Wh[(size_t)GEMM_M * GEMM_N];     // dynamic weights hi (78.6 MB)
__device__ __half g_Wl[(size_t)GEMM_M * GEMM_N];     // dynamic weights lo

// ---------------- PTX helpers (baseline PTX only) ----------------
__device__ __forceinline__ uint32_t smem_u32(const void* p) {
    uint32_t a;
    asm("{ .reg .u64 t; cvta.to.shared.u64 t, %1; cvt.u32.u64 %0, t; }" : "=r"(a) : "l"(p));
    return a;
}
__device__ __forceinline__ void cp16(uint32_t dst, const void* src) {
    asm volatile("cp.async.cg.shared.global [%0], [%1], 16;" :: "r"(dst), "l"(src) : "memory");
}
__device__ __forceinline__ void cp_commit() {
    asm volatile("cp.async.commit_group;" ::: "memory");
}
template <int N>
__device__ __forceinline__ void cp_wait() {
    asm volatile("cp.async.wait_group %0;" :: "n"(N) : "memory");
}
__device__ __forceinline__ void ldmatrix_x4(uint32_t& r0, uint32_t& r1, uint32_t& r2,
                                            uint32_t& r3, uint32_t addr) {
    asm volatile("ldmatrix.sync.aligned.m8n8.x4.shared.b16 {%0,%1,%2,%3}, [%4];"
                 : "=r"(r0), "=r"(r1), "=r"(r2), "=r"(r3) : "r"(addr));
}
__device__ __forceinline__ void mma16816(float* c, const uint32_t* a, const uint32_t* b) {
    asm volatile("mma.sync.aligned.m16n8k16.row.col.f32.f16.f16.f32 "
                 "{%0,%1,%2,%3}, {%4,%5,%6,%7}, {%8,%9}, {%0,%1,%2,%3};"
                 : "+f"(c[0]), "+f"(c[1]), "+f"(c[2]), "+f"(c[3])
                 : "r"(a[0]), "r"(a[1]), "r"(a[2]), "r"(a[3]), "r"(b[0]), "r"(b[1]));
}

// swizzle for 32-col (64B-row) tiles: 2 rows per 128B phase (gen_w)
__device__ __forceinline__ uint32_t swz(int r, int c) {
    return (uint32_t)(((r >> 1) << 7) + ((r & 1) << 6) + ((c ^ ((r >> 1) & 3)) << 4));
}
// swizzle for 64-col (128B-row) tiles (mix)
__device__ __forceinline__ uint32_t swz64(int r, int c) {
    return (uint32_t)((r << 7) + ((c ^ (r & 7)) << 4));
}

// ======================= split/prep kernels =======================
__global__ void split_qc_kernel(const float* __restrict__ qc,
                                __half* __restrict__ Ah, __half* __restrict__ Al) {
    int idx = blockIdx.x * blockDim.x + threadIdx.x;
    if (idx >= PAD_M * GEMM_K) return;
    float v = (idx < GEMM_M * GEMM_K) ? qc[idx] : 0.f;
    __half h = __float2half_rn(v);
    float lo = v - __half2float(h);
    Ah[idx] = h;
    Al[idx] = __float2half_rn(lo);
}

__global__ void split_w_kernel(const float* __restrict__ W,
                               __half* __restrict__ Bh, __half* __restrict__ Bl) {
    __shared__ float sm[32][33];
    const int n0 = blockIdx.x * 32;
    const int k0 = blockIdx.y * 32;
    const int tx = threadIdx.x, ty = threadIdx.y;
    sm[ty][tx] = W[(size_t)(k0 + ty) * GEMM_N + n0 + tx];
    __syncthreads();
    float v = sm[tx][ty];  // = W[k0+tx][n0+ty]
    __half h = __float2half_rn(v);
    float lo = v - __half2float(h);
    const size_t o = (size_t)(n0 + ty) * GEMM_K + k0 + tx;
    Bh[o] = h;
    Bl[o] = __float2half_rn(lo);
}

// ======================= split-fp16 HMMA GEMM =======================
// D = Ah*Bh + Ah*Bl + Al*Bh (fp32 accum); output stored as fp16 hi/lo pair.
#define TILE_BYTES  8192
#define STAGE_BYTES (4 * TILE_BYTES)
#define SMEM_GEMM   (2 * STAGE_BYTES)
#define NTILES      (GEMM_K / 32)

__device__ __forceinline__ void stage_load(uint32_t sbuf,
                                           const __half* __restrict__ gAh,
                                           const __half* __restrict__ gAl,
                                           const __half* __restrict__ gBh,
                                           const __half* __restrict__ gBl,
                                           int kc, int tid) {
#pragma unroll
    for (int t = 0; t < 2; ++t) {
        const int q = t * 256 + tid;
        const int r = q >> 2;
        const int c = q & 3;
        const uint32_t dst = swz(r, c);
        const size_t goff = (size_t)r * GEMM_K + kc + c * 8;
        cp16(sbuf + 0 * TILE_BYTES + dst, gAh + goff);
        cp16(sbuf + 1 * TILE_BYTES + dst, gAl + goff);
        cp16(sbuf + 2 * TILE_BYTES + dst, gBh + goff);
        cp16(sbuf + 3 * TILE_BYTES + dst, gBl + goff);
    }
}

__global__ __launch_bounds__(256)
void gen_w_mma_kernel(const __half* __restrict__ Ah, const __half* __restrict__ Al,
                      const __half* __restrict__ Bh, const __half* __restrict__ Bl,
                      const float* __restrict__ bias,
                      __half* __restrict__ oh, __half* __restrict__ ol) {
    extern __shared__ char smem[];
    const uint32_t sbase = smem_u32(smem);
    const int tid  = threadIdx.x;
    const int wid  = tid >> 5;
    const int lane = tid & 31;
    const int n0 = blockIdx.x * 128;
    const int m0 = blockIdx.y * 128;
    const int warp_m = wid & 1;
    const int warp_n = wid >> 1;

    const __half* gAh = Ah + (size_t)m0 * GEMM_K;
    const __half* gAl = Al + (size_t)m0 * GEMM_K;
    const __half* gBh = Bh + (size_t)n0 * GEMM_K;
    const __half* gBl = Bl + (size_t)n0 * GEMM_K;

    float acc[4][4][4];
#pragma unroll
    for (int i = 0; i < 4; ++i)
#pragma unroll
        for (int j = 0; j < 4; ++j)
#pragma unroll
            for (int k = 0; k < 4; ++k) acc[i][j][k] = 0.f;

    stage_load(sbase, gAh, gAl, gBh, gBl, 0, tid);
    cp_commit();
    stage_load(sbase + STAGE_BYTES, gAh, gAl, gBh, gBl, 32, tid);
    cp_commit();
    cp_wait<1>();
    __syncthreads();

    const int aRow = warp_m * 64 + (lane & 15);
    const int aSel = lane >> 4;
    const int bG   = lane >> 3;
    const int bRow = warp_n * 32 + ((bG >> 1) << 3) + (lane & 7);
    const int bSel = bG & 1;

#pragma unroll 1
    for (int t = 0; t < NTILES; ++t) {
        const uint32_t buf = sbase + (uint32_t)(t & 1) * STAGE_BYTES;
        const uint32_t sAh = buf;
        const uint32_t sAl = buf + TILE_BYTES;
        const uint32_t sBh = buf + 2 * TILE_BYTES;
        const uint32_t sBl = buf + 3 * TILE_BYTES;

#pragma unroll
        for (int k16 = 0; k16 < 2; ++k16) {
            const int cA = k16 * 2 + aSel;
            const int cB = k16 * 2 + bSel;

            uint32_t bH[4][2], bL[4][2];
#pragma unroll
            for (int ng = 0; ng < 2; ++ng) {
                const uint32_t off = swz(bRow + ng * 16, cB);
                uint32_t r0, r1, r2, r3;
                ldmatrix_x4(r0, r1, r2, r3, sBh + off);
                bH[2 * ng][0] = r0; bH[2 * ng][1] = r1;
                bH[2 * ng + 1][0] = r2; bH[2 * ng + 1][1] = r3;
                ldmatrix_x4(r0, r1, r2, r3, sBl + off);
                bL[2 * ng][0] = r0; bL[2 * ng][1] = r1;
                bL[2 * ng + 1][0] = r2; bL[2 * ng + 1][1] = r3;
            }

#pragma unroll
            for (int mi = 0; mi < 4; ++mi) {
                const uint32_t off = swz(aRow + mi * 16, cA);
                uint32_t aH[4], aL[4];
                ldmatrix_x4(aH[0], aH[1], aH[2], aH[3], sAh + off);
                ldmatrix_x4(aL[0], aL[1], aL[2], aL[3], sAl + off);
#pragma unroll
                for (int ni = 0; ni < 4; ++ni) {
                    mma16816(acc[mi][ni], aH, bH[ni]);
                    mma16816(acc[mi][ni], aH, bL[ni]);
                    mma16816(acc[mi][ni], aL, bH[ni]);
                }
            }
        }

        __syncthreads();
        if (t + 2 < NTILES) {
            stage_load(buf, gAh, gAl, gBh, gBl, (t + 2) * 32, tid);
            cp_commit();
            cp_wait<1>();
        } else if (t + 1 < NTILES) {
            cp_wait<0>();
        }
        __syncthreads();
    }

    // epilogue: bias, split to fp16 hi/lo, store half2
#pragma unroll
    for (int mi = 0; mi < 4; ++mi) {
        const int m_lo = m0 + warp_m * 64 + mi * 16 + (lane >> 2);
        const int m_hi = m_lo + 8;
#pragma unroll
        for (int ni = 0; ni < 4; ++ni) {
            const int n = n0 + warp_n * 32 + ni * 8 + (lane & 3) * 2;
            const float2 bv = *(const float2*)(bias + n);
#pragma unroll
            for (int half_i = 0; half_i < 2; ++half_i) {
                const int m = half_i ? m_hi : m_lo;
                if (m < GEMM_M) {
                    float s0 = acc[mi][ni][2 * half_i + 0] + bv.x;
                    float s1 = acc[mi][ni][2 * half_i + 1] + bv.y;
                    __half h0 = __float2half_rn(s0);
                    __half h1 = __float2half_rn(s1);
                    __half l0 = __float2half_rn(s0 - __half2float(h0));
                    __half l1 = __float2half_rn(s1 - __half2float(h1));
                    const size_t o = (size_t)m * GEMM_N + n;
                    *(__half2*)(oh + o) = __halves2half2(h0, h1);
                    *(__half2*)(ol + o) = __halves2half2(l0, l1);
                }
            }
        }
    }
}

// ================= mix kernel: tensor-core mixing + LayerNorm + ReLU =================
// One CTA per query, 4 warps, warp g computes [32 p x 64 e] = x[g] @ w[g]^T via
// split-fp16 HMMA (3 products). Then cross-warp LN over 256 channels + ReLU.
#define S_WH   0
#define S_WL   32768
#define S_XH   65536
#define S_XL   81920
#define S_RED1 98304
#define S_RED2 98816
#define S_MU   99328
#define S_RS   99456
#define MX_SMEM 99584

__global__ __launch_bounds__(128)
void mix_tc_kernel(const float* __restrict__ x,      // [2400, 32, 256]
                   const __half* __restrict__ wh,    // [2400, 16384]
                   const __half* __restrict__ wl,
                   const float* __restrict__ gamma,  // [256]
                   const float* __restrict__ beta,   // [256]
                   float* __restrict__ out)          // [2400, 32, 256]
{
    extern __shared__ char smem[];
    const uint32_t sbase = smem_u32(smem);
    float* smf = (float*)smem;

    const int tid  = threadIdx.x;
    const int wid  = tid >> 5;   // = group g
    const int lane = tid & 31;
    const int q    = blockIdx.x;
    const size_t wqb = (size_t)q * 16384;
    const size_t xqb = (size_t)q * 8192;

    // ---- stage w hi/lo via cp.async into swizzled tiles (group tile: 64x64, 8KB) ----
#pragma unroll
    for (int it = 0; it < 16; ++it) {
        const int idx = it * 128 + tid;       // 2048 chunks of 16B
        const int g   = idx >> 9;
        const int rem = idx & 511;
        const int e   = rem >> 3;
        const int c   = rem & 7;
        const uint32_t dst = (uint32_t)(g * 8192) + swz64(e, c);
        const size_t src = wqb + (size_t)g * 4096 + (size_t)e * 64 + c * 8;
        cp16(sbase + S_WH + dst, wh + src);
        cp16(sbase + S_WL + dst, wl + src);
    }
    cp_commit();

    // ---- load x fp32, split hi/lo, store to swizzled tiles (group tile: 32x64, 4KB) ----
#pragma unroll
    for (int it = 0; it < 8; ++it) {
        const int idx = it * 128 + tid;       // 1024 chunks
        const int g   = idx >> 8;
        const int rem = idx & 255;
        const int p   = rem >> 3;
        const int c   = rem & 7;
        const float* src = x + xqb + (size_t)p * 256 + g * 64 + c * 8;
        float4 f0 = *(const float4*)(src);
        float4 f1 = *(const float4*)(src + 4);
        float fv[8] = {f0.x, f0.y, f0.z, f0.w, f1.x, f1.y, f1.z, f1.w};
        uint32_t hh[4], ll[4];
#pragma unroll
        for (int i = 0; i < 4; ++i) {
            __half h0 = __float2half_rn(fv[2 * i]);
            __half h1 = __float2half_rn(fv[2 * i + 1]);
            __half l0 = __float2half_rn(fv[2 * i] - __half2float(h0));
            __half l1 = __float2half_rn(fv[2 * i + 1] - __half2float(h1));
            __half2 ph = __halves2half2(h0, h1);
            __half2 pl = __halves2half2(l0, l1);
            hh[i] = *(uint32_t*)&ph;
            ll[i] = *(uint32_t*)&pl;
        }
        const uint32_t dst = (uint32_t)(g * 4096) + swz64(p, c);
        asm volatile("st.shared.v4.b32 [%0], {%1,%2,%3,%4};"
                     :: "r"(sbase + S_XH + dst), "r"(hh[0]), "r"(hh[1]), "r"(hh[2]), "r"(hh[3])
                     : "memory");
        asm volatile("st.shared.v4.b32 [%0], {%1,%2,%3,%4};"
                     :: "r"(sbase + S_XL + dst), "r"(ll[0]), "r"(ll[1]), "r"(ll[2]), "r"(ll[3])
                     : "memory");
    }
    cp_wait<0>();
    __syncthreads();

    // ---- warp-level GEMM: M=32, N=64, K=64, 3 products ----
    const uint32_t sWH = sbase + S_WH + wid * 8192;
    const uint32_t sWL = sbase + S_WL + wid * 8192;
    const uint32_t sXH = sbase + S_XH + wid * 4096;
    const uint32_t sXL = sbase + S_XL + wid * 4096;

    float acc[2][8][4];
#pragma unroll
    for (int i = 0; i < 2; ++i)
#pragma unroll
        for (int j = 0; j < 8; ++j)
#pragma unroll
            for (int k = 0; k < 4; ++k) acc[i][j][k] = 0.f;

    const int aRow = lane & 15;
    const int aSel = lane >> 4;
    const int bG   = lane >> 3;
    const int bRow = ((bG >> 1) << 3) + (lane & 7);
    const int bSel = bG & 1;

#pragma unroll
    for (int kk = 0; kk < 4; ++kk) {
        const int cA = kk * 2 + aSel;
        const int cB = kk * 2 + bSel;

        uint32_t bH[8][2], bL[8][2];
#pragma unroll
        for (int ng = 0; ng < 4; ++ng) {
            const uint32_t off = swz64(bRow + ng * 16, cB);
            uint32_t r0, r1, r2, r3;
            ldmatrix_x4(r0, r1, r2, r3, sWH + off);
            bH[2 * ng][0] = r0; bH[2 * ng][1] = r1;
            bH[2 * ng + 1][0] = r2; bH[2 * ng + 1][1] = r3;
            ldmatrix_x4(r0, r1, r2, r3, sWL + off);
            bL[2 * ng][0] = r0; bL[2 * ng][1] = r1;
            bL[2 * ng + 1][0] = r2; bL[2 * ng + 1][1] = r3;
        }

#pragma unroll
        for (int mi = 0; mi < 2; ++mi) {
            const uint32_t off = swz64(aRow + mi * 16, cA);
            uint32_t aH[4], aL[4];
            ldmatrix_x4(aH[0], aH[1], aH[2], aH[3], sXH + off);
            ldmatrix_x4(aL[0], aL[1], aL[2], aL[3], sXL + off);
#pragma unroll
            for (int ni = 0; ni < 8; ++ni) {
                mma16816(acc[mi][ni], aH, bH[ni]);
                mma16816(acc[mi][ni], aH, bL[ni]);
                mma16816(acc[mi][ni], aL, bH[ni]);
            }
        }
    }

    // ---- LayerNorm partial sums (per-thread rows: p = mi*16 + h*8 + lane>>2) ----
    float* red1 = smf + (S_RED1 >> 2);
    float* red2 = smf + (S_RED2 >> 2);
    float* smu  = smf + (S_MU  >> 2);
    float* srs  = smf + (S_RS  >> 2);

#pragma unroll
    for (int mi = 0; mi < 2; ++mi) {
#pragma unroll
        for (int h = 0; h < 2; ++h) {
            float s1 = 0.f, s2 = 0.f;
#pragma unroll
            for (int ni = 0; ni < 8; ++ni) {
                float v0 = acc[mi][ni][2 * h + 0];
                float v1 = acc[mi][ni][2 * h + 1];
                s1 += v0 + v1;
                s2 += v0 * v0 + v1 * v1;
            }
            s1 += __shfl_xor_sync(0xFFFFFFFFu, s1, 1);
            s1 += __shfl_xor_sync(0xFFFFFFFFu, s1, 2);
            s2 += __shfl_xor_sync(0xFFFFFFFFu, s2, 1);
            s2 += __shfl_xor_sync(0xFFFFFFFFu, s2, 2);
            if ((lane & 3) == 0) {
                const int p = mi * 16 + h * 8 + (lane >> 2);
                red1[wid * 32 + p] = s1;
                red2[wid * 32 + p] = s2;
            }
        }
    }
    __syncthreads();

    if (tid < 32) {
        const int p = tid;
        float t1 = red1[p] + red1[32 + p] + red1[64 + p] + red1[96 + p];
        float t2 = red2[p] + red2[32 + p] + red2[64 + p] + red2[96 + p];
        float mu  = t1 * (1.f / 256.f);
        float var = t2 * (1.f / 256.f) - mu * mu;
        smu[p] = mu;
        srs[p] = rsqrtf(var + 1e-5f);
    }
    __syncthreads();

    // ---- apply LN + ReLU, store fp32 ----
    float2 gv[8], bv[8];
#pragma unroll
    for (int ni = 0; ni < 8; ++ni) {
        const int c = wid * 64 + ni * 8 + (lane & 3) * 2;
        gv[ni] = *(const float2*)(gamma + c);
        bv[ni] = *(const float2*)(beta + c);
    }

#pragma unroll
    for (int mi = 0; mi < 2; ++mi) {
#pragma unroll
        for (int h = 0; h < 2; ++h) {
            const int p = mi * 16 + h * 8 + (lane >> 2);
            const float mu = smu[p];
            const float rs = srs[p];
            float* orow = out + xqb + (size_t)p * 256;
#pragma unroll
            for (int ni = 0; ni < 8; ++ni) {
                const int c = wid * 64 + ni * 8 + (lane & 3) * 2;
                float2 v;
                v.x = fmaxf((acc[mi][ni][2 * h + 0] - mu) * rs * gv[ni].x + bv[ni].x, 0.f);
                v.y = fmaxf((acc[mi][ni][2 * h + 1] - mu) * rs * gv[ni].y + bv[ni].y, 0.f);
                *(float2*)(orow + c) = v;
            }
        }
    }
}

// ============================== launch ==============================
extern "C" void kernel_launch(void* const* d_in, const int* in_sizes, int n_in,
                              void* d_out, int out_size) {
    const float* x     = (const float*)d_in[0];  // [8,300,32,256]
    const float* qc    = (const float*)d_in[1];  // [8,300,256]
    const float* Wg    = (const float*)d_in[2];  // [256,16384]
    const float* bg    = (const float*)d_in[3];  // [16384]
    const float* gamma = (const float*)d_in[4];  // [256]
    const float* beta  = (const float*)d_in[5];  // [256]
    float* out = (float*)d_out;

    __half *ah, *al, *bh, *bl, *wh, *wl;
    cudaGetSymbolAddress((void**)&ah, g_Ah);
    cudaGetSymbolAddress((void**)&al, g_Al);
    cudaGetSymbolAddress((void**)&bh, g_Bh);
    cudaGetSymbolAddress((void**)&bl, g_Bl);
    cudaGetSymbolAddress((void**)&wh, g_Wh);
    cudaGetSymbolAddress((void**)&wl, g_Wl);

    // 1) fp16 hi/lo splits (+ transpose of W into [N,K] K-major)
    split_qc_kernel<<<(PAD_M * GEMM_K + 255) / 256, 256>>>(qc, ah, al);
    split_w_kernel<<<dim3(GEMM_N / 32, GEMM_K / 32), dim3(32, 32)>>>(Wg, bh, bl);

    // 2) split-fp16 HMMA GEMM: w = qc @ W_gen + bias -> fp16 hi/lo
    cudaFuncSetAttribute(gen_w_mma_kernel, cudaFuncAttributeMaxDynamicSharedMemorySize,
                         SMEM_GEMM);
    dim3 gridG(GEMM_N / 128, PAD_M / 128);  // (128, 19)
    gen_w_mma_kernel<<<gridG, 256, SMEM_GEMM>>>(ah, al, bh, bl, bg, wh, wl);

    // 3) tensor-core mixing + LN + ReLU
    cudaFuncSetAttribute(mix_tc_kernel, cudaFuncAttributeMaxDynamicSharedMemorySize,
                         MX_SMEM);
    mix_tc_kernel<<<GEMM_M, 128, MX_SMEM>>>(x, wh, wl, gamma, beta, out);
}